// round 2
// baseline (speedup 1.0000x reference)
#include <cuda_runtime.h>
#include <math.h>

#define NN   302
#define TT   2048
#define KK   33
#define TEX  2080          // TT + KK - 1
#define NOD  16
#define DTs  0.2f
#define CROP 16            // (TEX - TT)/2

// ---------------- scratch (static device globals; no allocs) ----------------
__device__ float g_sens[NN * TEX];          // sensory_input_extend
__device__ int   g_cnt[2 * NN];             // [0..NN): chem count, [NN..2NN): elec count
__device__ int   g_col[2][NN][NN];
__device__ float g_valw[2][NN][NN];

// ---------------- kernel 0: deterministic sparsification of W_chem/W_elec ---
__global__ void k_sparsify(const float* __restrict__ Wc, const float* __restrict__ We) {
    int m = blockIdx.x * blockDim.x + threadIdx.x;
    if (m >= NN) return;
    int c0 = 0, c1 = 0;
    for (int j = 0; j < NN; ++j) {
        float v = Wc[m * NN + j];
        if (v != 0.0f) { g_col[0][m][c0] = j; g_valw[0][m][c0] = v; ++c0; }
        float w = We[m * NN + j];
        if (w != 0.0f) { g_col[1][m][c1] = j; g_valw[1][m][c1] = w; ++c1; }
    }
    g_cnt[m] = c0;
    g_cnt[NN + m] = c1;
}

// ---------------- kernel 1: sensory_input_extend (N x TE) -------------------
__global__ void k_sensory(const float* __restrict__ odor,   // (16, TE)
                          const float* __restrict__ Wenc,   // (N, 16)
                          const float* __restrict__ benc,   // (N,)
                          const float* __restrict__ mask)   // (N,)
{
    int n = blockIdx.y;
    int t = blockIdx.x * blockDim.x + threadIdx.x;
    if (t >= TEX) return;
    float acc = 0.0f;
#pragma unroll
    for (int o = 0; o < NOD; ++o)
        acc = fmaf(Wenc[n * NOD + o], odor[o * TEX + t], acc);
    acc += benc[n];
    g_sens[n * TEX + t] = mask[n] * acc;
}

// ---------------- kernel 2: dwconvs + VAE sample + softplus -----------------
// writes: mu_v (sec2), logvar_v (sec3), sample_v (sec4), calcium_activation (sec5),
//         sensory_input (sec8)
__global__ void k_convsample(const float* __restrict__ fr,   // (N, TE)
                             const float* __restrict__ eps,  // (N, T)
                             const float* __restrict__ Wmf, const float* __restrict__ Wms,
                             const float* __restrict__ bmu,
                             const float* __restrict__ Wlf, const float* __restrict__ Wls,
                             const float* __restrict__ blv,
                             const float* __restrict__ waff, const float* __restrict__ baff,
                             float* __restrict__ out)
{
    __shared__ float s_fr[256 + KK - 1 + 1];
    __shared__ float s_se[256 + KK - 1 + 1];
    __shared__ float s_w[4 * KK];
    const int n  = blockIdx.y;
    const int tx = threadIdx.x;
    const int t0 = blockIdx.x * 256;

    for (int i = tx; i < 256 + KK - 1; i += 256) {
        s_fr[i] = fr[n * TEX + t0 + i];
        s_se[i] = g_sens[n * TEX + t0 + i];
    }
    if (tx < KK)               s_w[tx]           = Wmf[n * KK + tx];
    else if (tx < 2 * KK)      s_w[tx]           = Wms[n * KK + tx - KK];
    else if (tx < 3 * KK)      s_w[tx]           = Wlf[n * KK + tx - 2 * KK];
    else if (tx < 4 * KK)      s_w[tx]           = Wls[n * KK + tx - 3 * KK];
    __syncthreads();

    const int t = t0 + tx;
    float a = 0.f, b = 0.f, c = 0.f, d = 0.f;
#pragma unroll
    for (int k = 0; k < KK; ++k) {
        float xf = s_fr[tx + k];
        float xs = s_se[tx + k];
        a = fmaf(xf, s_w[k], a);
        b = fmaf(xs, s_w[KK + k], b);
        c = fmaf(xf, s_w[2 * KK + k], c);
        d = fmaf(xs, s_w[3 * KK + k], d);
    }
    float mu = a + b + bmu[n];
    float lv = c + d + blv[n];
    float sv = fmaf(expf(0.5f * lv), eps[n * TT + t], mu);
    float z  = fmaf(waff[n], sv, baff[n]);
    float ca = fmaxf(z, 0.0f) + log1pf(expf(-fabsf(z)));   // stable softplus

    const size_t NT = (size_t)NN * TT;
    const size_t idx = (size_t)n * TT + t;
    out[2 * NT + idx] = mu;
    out[3 * NT + idx] = lv;
    out[4 * NT + idx] = sv;
    out[5 * NT + idx] = ca;
    out[8 * NT + idx] = s_se[tx + CROP];   // sensory_input (cropped)
}

// ---------------- kernel 3: sparse recurrent + voltage update ---------------
// reads sample_v (sec4), sensory_input (sec8); writes recurrent_in (sec7),
// mu_neuron_voltage_prob (sec0)
__global__ void k_recurrent(const float* __restrict__ bias,
                            const float* __restrict__ tau,
                            float* __restrict__ out)
{
    __shared__ int   sc_col[NN], se_col[NN];
    __shared__ float sc_val[NN], se_val[NN];
    __shared__ int   s_cnt[2];
    const int n  = blockIdx.y;
    const int tx = threadIdx.x;
    if (tx < 2) s_cnt[tx] = g_cnt[tx * NN + n];
    __syncthreads();
    const int nc = s_cnt[0], ne = s_cnt[1];
    for (int i = tx; i < nc; i += 256) { sc_col[i] = g_col[0][n][i]; sc_val[i] = g_valw[0][n][i]; }
    for (int i = tx; i < ne; i += 256) { se_col[i] = g_col[1][n][i]; se_val[i] = g_valw[1][n][i]; }
    __syncthreads();

    const size_t NT  = (size_t)NN * TT;
    const int t      = blockIdx.x * 256 + tx;
    const float* sv_all = out + 4 * NT;

    float a1 = 0.f;
    for (int i = 0; i < nc; ++i) {
        float x = sv_all[(size_t)sc_col[i] * TT + t];
        a1 = fmaf(sc_val[i], fmaxf(x, 0.0f), a1);
    }
    float a2 = 0.f;
    for (int i = 0; i < ne; ++i) {
        float x = sv_all[(size_t)se_col[i] * TT + t];
        a2 = fmaf(se_val[i], x, a2);
    }
    const size_t idx = (size_t)n * TT + t;
    float rec = a1 + a2 + out[8 * NT + idx];
    float sv  = sv_all[idx];
    float mun = sv + (DTs / tau[n]) * (-sv + rec + bias[n]);
    out[7 * NT + idx] = rec;
    out[0 * NT + idx] = mun;
}

// ---------------- kernel 4: exponential-kernel IIR scan ---------------------
// mu_calcium[t] = r*mu_calcium[t-1] + ca[t], seeded so that the init*r^t term
// appears; writes mu_calcium_prob (sec6) and mu_fluorescence (sec1).
// Warp-per-neuron segmented scan: 64 elems/lane, affine shuffle scan.
__global__ void k_scan(const float* __restrict__ ffull,   // (N, T)
                       const float* __restrict__ ctau,
                       const float* __restrict__ scale,
                       const float* __restrict__ shift,
                       float* __restrict__ out)
{
    __shared__ float sbuf[4][TT + 32];   // padded: idx = i + i/64 (conflict-free)
    const int w    = threadIdx.x >> 5;
    const int lane = threadIdx.x & 31;
    const int n    = blockIdx.x * 4 + w;
    if (n >= NN) return;

    const size_t NT = (size_t)NN * TT;
    const float* ca = out + 5 * NT + (size_t)n * TT;

    // coalesced stage-in
    for (int i = lane; i < TT; i += 32)
        sbuf[w][i + (i >> 6)] = ca[i];
    __syncwarp();

    const float r = expf(-DTs / ctau[n]);
    float f = r;                      // r^64 by repeated squaring
#pragma unroll
    for (int q = 0; q < 6; ++q) f *= f;

    // local segment: e = sum_j ca[j] * r^(63-j)  via sequential recurrence
    const int base = lane * 65;
    float e = 0.f;
#pragma unroll 8
    for (int j = 0; j < 64; ++j)
        e = fmaf(r, e, sbuf[w][base + j]);

    // inclusive scan of affine maps (f, e): later ∘ earlier
    float F = f, E = e;
#pragma unroll
    for (int d = 1; d < 32; d <<= 1) {
        float Fp = __shfl_up_sync(0xffffffffu, F, d);
        float Ep = __shfl_up_sync(0xffffffffu, E, d);
        if (lane >= d) { E = fmaf(F, Ep, E); F = F * Fp; }
    }

    const float init = (ffull[(size_t)n * TT] - shift[n]) / scale[n];
    const float x0   = init / r;      // m[-1] seed so m[0] = init + ca[0]
    float Fe = __shfl_up_sync(0xffffffffu, F, 1);
    float Ee = __shfl_up_sync(0xffffffffu, E, 1);
    float carry = (lane == 0) ? x0 : fmaf(Fe, x0, Ee);

    // second pass: materialize scan into smem
    float cacc = carry;
#pragma unroll 8
    for (int j = 0; j < 64; ++j) {
        cacc = fmaf(r, cacc, sbuf[w][base + j]);
        sbuf[w][base + j] = cacc;
    }
    __syncwarp();

    // coalesced stage-out: mu_calcium (sec6), fluorescence (sec1)
    const float sc = scale[n], sh = shift[n];
    float* o6 = out + 6 * NT + (size_t)n * TT;
    float* o1 = out + 1 * NT + (size_t)n * TT;
    for (int i = lane; i < TT; i += 32) {
        float m = sbuf[w][i + (i >> 6)];
        o6[i] = m;
        o1[i] = fmaf(sc, m, sh);
    }
}

// ---------------- launch ----------------------------------------------------
extern "C" void kernel_launch(void* const* d_in, const int* in_sizes, int n_in,
                              void* d_out, int out_size)
{
    const float* fr    = (const float*)d_in[0];
    const float* ffull = (const float*)d_in[1];
    const float* odor  = (const float*)d_in[2];
    const float* eps   = (const float*)d_in[3];
    const float* Wenc  = (const float*)d_in[4];
    const float* benc  = (const float*)d_in[5];
    const float* mask  = (const float*)d_in[6];
    const float* Wmf   = (const float*)d_in[7];
    const float* Wms   = (const float*)d_in[8];
    const float* bmu   = (const float*)d_in[9];
    const float* Wlf   = (const float*)d_in[10];
    const float* Wls   = (const float*)d_in[11];
    const float* blv   = (const float*)d_in[12];
    const float* Wc    = (const float*)d_in[13];
    const float* We    = (const float*)d_in[14];
    const float* bias  = (const float*)d_in[15];
    const float* tau   = (const float*)d_in[16];
    const float* waff  = (const float*)d_in[17];
    const float* baff  = (const float*)d_in[18];
    const float* scale = (const float*)d_in[19];
    const float* shift = (const float*)d_in[20];
    const float* ctau  = (const float*)d_in[21];
    float* out = (float*)d_out;

    k_sparsify<<<1, 320>>>(Wc, We);
    k_sensory<<<dim3((TEX + 255) / 256, NN), 256>>>(odor, Wenc, benc, mask);
    k_convsample<<<dim3(TT / 256, NN), 256>>>(fr, eps, Wmf, Wms, bmu, Wlf, Wls, blv,
                                              waff, baff, out);
    k_recurrent<<<dim3(TT / 256, NN), 256>>>(bias, tau, out);
    k_scan<<<(NN + 3) / 4, 128>>>(ffull, ctau, scale, shift, out);
}

// round 3
// speedup vs baseline: 1.4331x; 1.4331x over previous
#include <cuda_runtime.h>
#include <math.h>

#define NN   302
#define TT   2048
#define TT4  512           // TT / 4
#define KK   33
#define TEX  2080          // TT + KK - 1
#define NOD  16
#define DTs  0.2f
#define CROP 16            // (TEX - TT)/2
#define NTs  ((size_t)NN * TT)

#define CONV_BLOCKS  (NN * 8)          // 2416: 8 chunks of 256 t per neuron
#define SPAR_BLOCKS  38                // 8 warps/block, warp-per-row
#define REC_BLOCKS   (NN * 2)          // 604: 2 chunks of 1024 t per neuron
#define SCAN_BLOCKS  38                // 8 warps/block, warp-per-neuron

// ---------------- scratch (static device globals; no allocs) ----------------
__device__ int   g_cnt[2 * NN];
__device__ int   g_col[2][NN][NN];
__device__ float g_valw[2][NN][NN];

// ============================================================================
// K1: fused sensory-encode + depthwise convs + VAE sample + softplus
//     PLUS sparsification of W_chem/W_elec (extra blocks, warp-per-row ballot)
// writes out sections 2,3,4,5,8
// ============================================================================
__global__ void __launch_bounds__(256)
k_main(const float* __restrict__ fr,    // (N, TE)
       const float* __restrict__ odor,  // (16, TE)
       const float* __restrict__ Wenc,  // (N, 16)
       const float* __restrict__ benc,
       const float* __restrict__ mask,
       const float* __restrict__ eps,   // (N, T)
       const float* __restrict__ Wmf, const float* __restrict__ Wms,
       const float* __restrict__ bmu,
       const float* __restrict__ Wlf, const float* __restrict__ Wls,
       const float* __restrict__ blv,
       const float* __restrict__ waff, const float* __restrict__ baff,
       const float* __restrict__ Wc, const float* __restrict__ We,
       float* __restrict__ out)
{
    const int tx = threadIdx.x;

    if (blockIdx.x >= CONV_BLOCKS) {
        // ---------------- sparsify branch: warp per matrix row ----------------
        const int sb   = blockIdx.x - CONV_BLOCKS;
        const int lane = tx & 31;
        const int m    = sb * 8 + (tx >> 5);
        if (m >= NN) return;
        int c0 = 0, c1 = 0;
        for (int jb = 0; jb < NN; jb += 32) {
            const int j = jb + lane;
            float v = (j < NN) ? Wc[m * NN + j] : 0.0f;
            unsigned mk = __ballot_sync(0xffffffffu, v != 0.0f);
            if (v != 0.0f) {
                int p = c0 + __popc(mk & ((1u << lane) - 1u));
                g_col[0][m][p] = j; g_valw[0][m][p] = v;
            }
            c0 += __popc(mk);
            float w = (j < NN) ? We[m * NN + j] : 0.0f;
            mk = __ballot_sync(0xffffffffu, w != 0.0f);
            if (w != 0.0f) {
                int p = c1 + __popc(mk & ((1u << lane) - 1u));
                g_col[1][m][p] = j; g_valw[1][m][p] = w;
            }
            c1 += __popc(mk);
        }
        if (lane == 0) { g_cnt[m] = c0; g_cnt[NN + m] = c1; }
        return;
    }

    // ---------------- conv/sample branch ----------------
    __shared__ float s_fr[288];
    __shared__ float s_se[288];
    __shared__ float s_w[4 * KK];
    const int n  = blockIdx.x >> 3;
    const int t0 = (blockIdx.x & 7) * 256;

    // stage fr halo + compute sensory_input_extend on the fly
    const float msk = mask[n];
    const float be  = benc[n];
    for (int i = tx; i < 288; i += 256) {
        s_fr[i] = fr[n * TEX + t0 + i];
        float acc = 0.0f;
#pragma unroll
        for (int o = 0; o < NOD; ++o)
            acc = fmaf(__ldg(&Wenc[n * NOD + o]), odor[o * TEX + t0 + i], acc);
        s_se[i] = msk * (acc + be);
    }
    if (tx < KK)          s_w[tx] = Wmf[n * KK + tx];
    else if (tx < 2 * KK) s_w[tx] = Wms[n * KK + tx - KK];
    else if (tx < 3 * KK) s_w[tx] = Wlf[n * KK + tx - 2 * KK];
    else if (tx < 4 * KK) s_w[tx] = Wls[n * KK + tx - 3 * KK];
    __syncthreads();

    const int t = t0 + tx;
    float a = 0.f, b = 0.f, c = 0.f, d = 0.f;
#pragma unroll
    for (int k = 0; k < KK; ++k) {
        float xf = s_fr[tx + k];
        float xs = s_se[tx + k];
        a = fmaf(xf, s_w[k], a);
        b = fmaf(xs, s_w[KK + k], b);
        c = fmaf(xf, s_w[2 * KK + k], c);
        d = fmaf(xs, s_w[3 * KK + k], d);
    }
    float mu = a + b + bmu[n];
    float lv = c + d + blv[n];
    float sv = fmaf(expf(0.5f * lv), eps[n * TT + t], mu);
    float z  = fmaf(waff[n], sv, baff[n]);
    float ca = fmaxf(z, 0.0f) + log1pf(expf(-fabsf(z)));   // stable softplus

    const size_t idx = (size_t)n * TT + t;
    out[2 * NTs + idx] = mu;
    out[3 * NTs + idx] = lv;
    out[4 * NTs + idx] = sv;
    out[5 * NTs + idx] = ca;
    out[8 * NTs + idx] = s_se[tx + CROP];
}

// ============================================================================
// K2: sparse recurrent + voltage update (float4)  PLUS  IIR scan (extra blocks)
// recurrent: reads sec4, sec8 -> writes sec7, sec0
// scan:      reads sec5       -> writes sec6, sec1
// ============================================================================
__global__ void __launch_bounds__(256)
k_epi(const float* __restrict__ bias,
      const float* __restrict__ tau,
      const float* __restrict__ ffull,
      const float* __restrict__ ctau,
      const float* __restrict__ scale,
      const float* __restrict__ shift,
      float* __restrict__ out)
{
    const int tx = threadIdx.x;

    if (blockIdx.x >= REC_BLOCKS) {
        // ---------------- scan branch: warp per neuron, no smem ----------------
        const int sb   = blockIdx.x - REC_BLOCKS;
        const int lane = tx & 31;
        const int n    = sb * 8 + (tx >> 5);
        if (n >= NN) return;

        const float* ca = out + 5 * NTs + (size_t)n * TT;
        const float r = expf(-DTs / ctau[n]);
        float f = r;
#pragma unroll
        for (int q = 0; q < 6; ++q) f *= f;       // r^64

        const int base = lane * 64;
        float e = 0.f;
#pragma unroll 16
        for (int j = 0; j < 64; ++j)
            e = fmaf(r, e, __ldg(&ca[base + j]));

        // inclusive scan of affine maps (f, e)
        float F = f, E = e;
#pragma unroll
        for (int dd = 1; dd < 32; dd <<= 1) {
            float Fp = __shfl_up_sync(0xffffffffu, F, dd);
            float Ep = __shfl_up_sync(0xffffffffu, E, dd);
            if (lane >= dd) { E = fmaf(F, Ep, E); F = F * Fp; }
        }
        const float init = (ffull[(size_t)n * TT] - shift[n]) / scale[n];
        const float x0   = init / r;              // m[-1] seed: m[0] = init + ca[0]
        float Fe = __shfl_up_sync(0xffffffffu, F, 1);
        float Ee = __shfl_up_sync(0xffffffffu, E, 1);
        float carry = (lane == 0) ? x0 : fmaf(Fe, x0, Ee);

        const float sc = scale[n], sh = shift[n];
        float* o6 = out + 6 * NTs + (size_t)n * TT + base;
        float* o1 = out + 1 * NTs + (size_t)n * TT + base;
        float cacc = carry;
#pragma unroll 16
        for (int j = 0; j < 64; ++j) {
            cacc = fmaf(r, cacc, __ldg(&ca[base + j]));
            o6[j] = cacc;
            o1[j] = fmaf(sc, cacc, sh);
        }
        return;
    }

    // ---------------- recurrent branch: float4, 1024 t per block ----------------
    __shared__ int   sc_col[NN], se_col[NN];
    __shared__ float sc_val[NN], se_val[NN];
    __shared__ int   s_cnt[2];
    const int n  = blockIdx.x >> 1;
    const int t4 = (blockIdx.x & 1) * 256 + tx;    // float4 index within row

    if (tx < 2) s_cnt[tx] = g_cnt[tx * NN + n];
    __syncthreads();
    const int nc = s_cnt[0], ne = s_cnt[1];
    for (int i = tx; i < nc; i += 256) { sc_col[i] = g_col[0][n][i]; sc_val[i] = g_valw[0][n][i]; }
    for (int i = tx; i < ne; i += 256) { se_col[i] = g_col[1][n][i]; se_val[i] = g_valw[1][n][i]; }
    __syncthreads();

    const float4* sv4 = (const float4*)(out + 4 * NTs);

    float4 a1 = make_float4(0.f, 0.f, 0.f, 0.f);
    for (int i = 0; i < nc; ++i) {
        float4 x = sv4[(size_t)sc_col[i] * TT4 + t4];
        float v  = sc_val[i];
        a1.x = fmaf(v, fmaxf(x.x, 0.f), a1.x);
        a1.y = fmaf(v, fmaxf(x.y, 0.f), a1.y);
        a1.z = fmaf(v, fmaxf(x.z, 0.f), a1.z);
        a1.w = fmaf(v, fmaxf(x.w, 0.f), a1.w);
    }
    float4 a2 = make_float4(0.f, 0.f, 0.f, 0.f);
    for (int i = 0; i < ne; ++i) {
        float4 x = sv4[(size_t)se_col[i] * TT4 + t4];
        float v  = se_val[i];
        a2.x = fmaf(v, x.x, a2.x);
        a2.y = fmaf(v, x.y, a2.y);
        a2.z = fmaf(v, x.z, a2.z);
        a2.w = fmaf(v, x.w, a2.w);
    }

    const size_t ridx = (size_t)n * TT4 + t4;
    float4 sen = ((const float4*)(out + 8 * NTs))[ridx];
    float4 sv  = sv4[ridx];
    float4 rec, mun;
    const float g  = DTs / tau[n];
    const float bi = bias[n];
    rec.x = a1.x + a2.x + sen.x;  rec.y = a1.y + a2.y + sen.y;
    rec.z = a1.z + a2.z + sen.z;  rec.w = a1.w + a2.w + sen.w;
    mun.x = sv.x + g * (-sv.x + rec.x + bi);
    mun.y = sv.y + g * (-sv.y + rec.y + bi);
    mun.z = sv.z + g * (-sv.z + rec.z + bi);
    mun.w = sv.w + g * (-sv.w + rec.w + bi);
    ((float4*)(out + 7 * NTs))[ridx] = rec;
    ((float4*)(out + 0 * NTs))[ridx] = mun;
}

// ---------------- launch ----------------------------------------------------
extern "C" void kernel_launch(void* const* d_in, const int* in_sizes, int n_in,
                              void* d_out, int out_size)
{
    const float* fr    = (const float*)d_in[0];
    const float* ffull = (const float*)d_in[1];
    const float* odor  = (const float*)d_in[2];
    const float* eps   = (const float*)d_in[3];
    const float* Wenc  = (const float*)d_in[4];
    const float* benc  = (const float*)d_in[5];
    const float* mask  = (const float*)d_in[6];
    const float* Wmf   = (const float*)d_in[7];
    const float* Wms   = (const float*)d_in[8];
    const float* bmu   = (const float*)d_in[9];
    const float* Wlf   = (const float*)d_in[10];
    const float* Wls   = (const float*)d_in[11];
    const float* blv   = (const float*)d_in[12];
    const float* Wc    = (const float*)d_in[13];
    const float* We    = (const float*)d_in[14];
    const float* bias  = (const float*)d_in[15];
    const float* tau   = (const float*)d_in[16];
    const float* waff  = (const float*)d_in[17];
    const float* baff  = (const float*)d_in[18];
    const float* scale = (const float*)d_in[19];
    const float* shift = (const float*)d_in[20];
    const float* ctau  = (const float*)d_in[21];
    float* out = (float*)d_out;

    k_main<<<CONV_BLOCKS + SPAR_BLOCKS, 256>>>(fr, odor, Wenc, benc, mask, eps,
                                               Wmf, Wms, bmu, Wlf, Wls, blv,
                                               waff, baff, Wc, We, out);
    k_epi<<<REC_BLOCKS + SCAN_BLOCKS, 256>>>(bias, tau, ffull, ctau, scale, shift, out);
}

// round 4
// speedup vs baseline: 2.3853x; 1.6644x over previous
#include <cuda_runtime.h>
#include <math.h>

#define NN   302
#define TT   2048
#define TT4  512           // TT / 4
#define KK   33
#define TEX  2080          // TT + KK - 1
#define NOD  16
#define DTs  0.2f
#define CROP 16            // (TEX - TT)/2
#define NTs  ((size_t)NN * TT)
#define NNP  312           // padded row capacity (mult of 8, >= NN+7)

#define CONV_BLOCKS  (NN * 8)          // 2416: 8 chunks of 256 t per neuron
#define SPAR_BLOCKS  38                // 8 warps/block, warp-per-row

// ---------------- scratch (static device globals; no allocs) ----------------
__device__ int   g_cnt[2 * NN];        // padded counts (multiple of 4)
__device__ int   g_col[2][NN][NNP];
__device__ float g_valw[2][NN][NNP];

// ============================================================================
// K1: fused sensory-encode + depthwise convs + VAE sample + softplus
//     PLUS sparsification of W_chem/W_elec (extra blocks, warp-per-row ballot)
// writes out sections 2,3,4,5,8
// ============================================================================
__global__ void __launch_bounds__(256)
k_main(const float* __restrict__ fr,    // (N, TE)
       const float* __restrict__ odor,  // (16, TE)
       const float* __restrict__ Wenc,  // (N, 16)
       const float* __restrict__ benc,
       const float* __restrict__ mask,
       const float* __restrict__ eps,   // (N, T)
       const float* __restrict__ Wmf, const float* __restrict__ Wms,
       const float* __restrict__ bmu,
       const float* __restrict__ Wlf, const float* __restrict__ Wls,
       const float* __restrict__ blv,
       const float* __restrict__ waff, const float* __restrict__ baff,
       const float* __restrict__ Wc, const float* __restrict__ We,
       float* __restrict__ out)
{
    const int tx = threadIdx.x;

    if (blockIdx.x >= CONV_BLOCKS) {
        // ---------------- sparsify branch: warp per matrix row ----------------
        const int sb   = blockIdx.x - CONV_BLOCKS;
        const int lane = tx & 31;
        const int m    = sb * 8 + (tx >> 5);
        if (m >= NN) return;
        int c0 = 0, c1 = 0;
        for (int jb = 0; jb < NN; jb += 32) {
            const int j = jb + lane;
            float v = (j < NN) ? Wc[m * NN + j] : 0.0f;
            unsigned mk = __ballot_sync(0xffffffffu, v != 0.0f);
            if (v != 0.0f) {
                int p = c0 + __popc(mk & ((1u << lane) - 1u));
                g_col[0][m][p] = j; g_valw[0][m][p] = v;
            }
            c0 += __popc(mk);
            float w = (j < NN) ? We[m * NN + j] : 0.0f;
            mk = __ballot_sync(0xffffffffu, w != 0.0f);
            if (w != 0.0f) {
                int p = c1 + __popc(mk & ((1u << lane) - 1u));
                g_col[1][m][p] = j; g_valw[1][m][p] = w;
            }
            c1 += __popc(mk);
        }
        // pad to multiple of 4 with exact no-op entries (col 0, val 0)
        int c0p = (c0 + 3) & ~3;
        int c1p = (c1 + 3) & ~3;
        if (lane < c0p - c0) { g_col[0][m][c0 + lane] = 0; g_valw[0][m][c0 + lane] = 0.f; }
        if (lane < c1p - c1) { g_col[1][m][c1 + lane] = 0; g_valw[1][m][c1 + lane] = 0.f; }
        if (lane == 0) { g_cnt[m] = c0p; g_cnt[NN + m] = c1p; }
        return;
    }

    // ---------------- conv/sample branch ----------------
    __shared__ float s_fr[288];
    __shared__ float s_se[288];
    __shared__ float s_w[4 * KK];
    const int n  = blockIdx.x >> 3;
    const int t0 = (blockIdx.x & 7) * 256;

    const float msk = mask[n];
    const float be  = benc[n];
    for (int i = tx; i < 288; i += 256) {
        s_fr[i] = fr[n * TEX + t0 + i];
        float acc = 0.0f;
#pragma unroll
        for (int o = 0; o < NOD; ++o)
            acc = fmaf(__ldg(&Wenc[n * NOD + o]), odor[o * TEX + t0 + i], acc);
        s_se[i] = msk * (acc + be);
    }
    if (tx < KK)          s_w[tx] = Wmf[n * KK + tx];
    else if (tx < 2 * KK) s_w[tx] = Wms[n * KK + tx - KK];
    else if (tx < 3 * KK) s_w[tx] = Wlf[n * KK + tx - 2 * KK];
    else if (tx < 4 * KK) s_w[tx] = Wls[n * KK + tx - 3 * KK];
    __syncthreads();

    const int t = t0 + tx;
    float a = 0.f, b = 0.f, c = 0.f, d = 0.f;
#pragma unroll
    for (int k = 0; k < KK; ++k) {
        float xf = s_fr[tx + k];
        float xs = s_se[tx + k];
        a = fmaf(xf, s_w[k], a);
        b = fmaf(xs, s_w[KK + k], b);
        c = fmaf(xf, s_w[2 * KK + k], c);
        d = fmaf(xs, s_w[3 * KK + k], d);
    }
    float mu = a + b + bmu[n];
    float lv = c + d + blv[n];
    float sv = fmaf(expf(0.5f * lv), eps[n * TT + t], mu);
    float z  = fmaf(waff[n], sv, baff[n]);
    float ca = fmaxf(z, 0.0f) + log1pf(expf(-fabsf(z)));   // stable softplus

    const size_t idx = (size_t)n * TT + t;
    out[2 * NTs + idx] = mu;
    out[3 * NTs + idx] = lv;
    out[4 * NTs + idx] = sv;
    out[5 * NTs + idx] = ca;
    out[8 * NTs + idx] = s_se[tx + CROP];
}

// ============================================================================
// K2: sparse recurrent + voltage update.  One block per neuron, 256 threads,
// each thread handles 8 time steps (two float4s). Lists padded to mult of 4
// -> fixed-stride loop with unrolled inner body (8 float4 LDGs in flight).
// ============================================================================
__global__ void __launch_bounds__(256)
k_rec(const float* __restrict__ bias,
      const float* __restrict__ tau,
      float* __restrict__ out)
{
    __shared__ int   sc_col[NNP], se_col[NNP];
    __shared__ float sc_val[NNP], se_val[NNP];
    __shared__ int   s_cnt[2];
    const int n  = blockIdx.x;
    const int tx = threadIdx.x;
    if (tx < 2) s_cnt[tx] = g_cnt[tx * NN + n];
    __syncthreads();
    const int nc = s_cnt[0], ne = s_cnt[1];
    for (int i = tx; i < nc; i += 256) { sc_col[i] = g_col[0][n][i]; sc_val[i] = g_valw[0][n][i]; }
    for (int i = tx; i < ne; i += 256) { se_col[i] = g_col[1][n][i]; se_val[i] = g_valw[1][n][i]; }
    __syncthreads();

    const float4* sv4 = (const float4*)(out + 4 * NTs);
    const int ta = tx;           // float4 index 0..255
    const int tb = tx + 256;     // float4 index 256..511

    float4 A = make_float4(0.f, 0.f, 0.f, 0.f);
    float4 B = make_float4(0.f, 0.f, 0.f, 0.f);
    for (int i = 0; i < nc; i += 4) {
#pragma unroll
        for (int u = 0; u < 4; ++u) {
            const size_t row = (size_t)sc_col[i + u] * TT4;
            float4 xa = sv4[row + ta];
            float4 xb = sv4[row + tb];
            const float v = sc_val[i + u];
            A.x = fmaf(v, fmaxf(xa.x, 0.f), A.x);
            A.y = fmaf(v, fmaxf(xa.y, 0.f), A.y);
            A.z = fmaf(v, fmaxf(xa.z, 0.f), A.z);
            A.w = fmaf(v, fmaxf(xa.w, 0.f), A.w);
            B.x = fmaf(v, fmaxf(xb.x, 0.f), B.x);
            B.y = fmaf(v, fmaxf(xb.y, 0.f), B.y);
            B.z = fmaf(v, fmaxf(xb.z, 0.f), B.z);
            B.w = fmaf(v, fmaxf(xb.w, 0.f), B.w);
        }
    }
    for (int i = 0; i < ne; i += 4) {
#pragma unroll
        for (int u = 0; u < 4; ++u) {
            const size_t row = (size_t)se_col[i + u] * TT4;
            float4 xa = sv4[row + ta];
            float4 xb = sv4[row + tb];
            const float v = se_val[i + u];
            A.x = fmaf(v, xa.x, A.x);  A.y = fmaf(v, xa.y, A.y);
            A.z = fmaf(v, xa.z, A.z);  A.w = fmaf(v, xa.w, A.w);
            B.x = fmaf(v, xb.x, B.x);  B.y = fmaf(v, xb.y, B.y);
            B.z = fmaf(v, xb.z, B.z);  B.w = fmaf(v, xb.w, B.w);
        }
    }

    const float g  = DTs / tau[n];
    const float bi = bias[n];
    const float4* sen4 = (const float4*)(out + 8 * NTs);
    float4* rec4 = (float4*)(out + 7 * NTs);
    float4* mun4 = (float4*)(out + 0 * NTs);

#pragma unroll
    for (int h = 0; h < 2; ++h) {
        const size_t ridx = (size_t)n * TT4 + (h ? tb : ta);
        float4 acc = h ? B : A;
        float4 sen = sen4[ridx];
        float4 sv  = sv4[ridx];
        float4 rec, mun;
        rec.x = acc.x + sen.x;  rec.y = acc.y + sen.y;
        rec.z = acc.z + sen.z;  rec.w = acc.w + sen.w;
        mun.x = sv.x + g * (-sv.x + rec.x + bi);
        mun.y = sv.y + g * (-sv.y + rec.y + bi);
        mun.z = sv.z + g * (-sv.z + rec.z + bi);
        mun.w = sv.w + g * (-sv.w + rec.w + bi);
        rec4[ridx] = rec;
        mun4[ridx] = mun;
    }
}

// ============================================================================
// K3: exponential-kernel IIR scan, warp-per-neuron with smem staging.
// Padded layout P(e) = e + 4*(e>>6): float4-aligned, coalesced global I/O.
// ============================================================================
#define SCW 2                         // warps per block
__global__ void __launch_bounds__(32 * SCW)
k_scan(const float* __restrict__ ffull,
       const float* __restrict__ ctau,
       const float* __restrict__ scale,
       const float* __restrict__ shift,
       float* __restrict__ out)
{
    __shared__ float sbuf[SCW][TT + 4 * 32];   // P(e) = e + 4*(e>>6)
    const int w    = threadIdx.x >> 5;
    const int lane = threadIdx.x & 31;
    const int n    = blockIdx.x * SCW + w;
    if (n >= NN) return;

    const float4* ca4 = (const float4*)(out + 5 * NTs + (size_t)n * TT);

    // coalesced stage-in (float4; pad keeps 16B alignment: 4*(i>>4) per vec idx)
    for (int i = lane; i < TT4; i += 32) {
        float4 v = ca4[i];
        *(float4*)&sbuf[w][4 * i + 4 * (i >> 4)] = v;
    }
    __syncwarp();

    const float r = expf(-DTs / ctau[n]);
    float f = r;
#pragma unroll
    for (int q = 0; q < 6; ++q) f *= f;          // r^64

    // local segment: e = sum_j ca[j] * r^(63-j)
    const int base = lane * 68;                  // P(64*lane)
    float e = 0.f;
#pragma unroll 16
    for (int j = 0; j < 64; ++j)
        e = fmaf(r, e, sbuf[w][base + j]);

    // inclusive scan of affine maps (f, e)
    float F = f, E = e;
#pragma unroll
    for (int d = 1; d < 32; d <<= 1) {
        float Fp = __shfl_up_sync(0xffffffffu, F, d);
        float Ep = __shfl_up_sync(0xffffffffu, E, d);
        if (lane >= d) { E = fmaf(F, Ep, E); F = F * Fp; }
    }

    const float init = (ffull[(size_t)n * TT] - shift[n]) / scale[n];
    const float x0   = init / r;                 // m[-1] seed: m[0] = init + ca[0]
    float Fe = __shfl_up_sync(0xffffffffu, F, 1);
    float Ee = __shfl_up_sync(0xffffffffu, E, 1);
    float carry = (lane == 0) ? x0 : fmaf(Fe, x0, Ee);

    // second pass: materialize scan into smem
    float cacc = carry;
#pragma unroll 16
    for (int j = 0; j < 64; ++j) {
        cacc = fmaf(r, cacc, sbuf[w][base + j]);
        sbuf[w][base + j] = cacc;
    }
    __syncwarp();

    // coalesced stage-out
    const float sc = scale[n], sh = shift[n];
    float4* o6 = (float4*)(out + 6 * NTs + (size_t)n * TT);
    float4* o1 = (float4*)(out + 1 * NTs + (size_t)n * TT);
    for (int i = lane; i < TT4; i += 32) {
        float4 m = *(const float4*)&sbuf[w][4 * i + 4 * (i >> 4)];
        o6[i] = m;
        float4 fl;
        fl.x = fmaf(sc, m.x, sh); fl.y = fmaf(sc, m.y, sh);
        fl.z = fmaf(sc, m.z, sh); fl.w = fmaf(sc, m.w, sh);
        o1[i] = fl;
    }
}

// ---------------- launch ----------------------------------------------------
extern "C" void kernel_launch(void* const* d_in, const int* in_sizes, int n_in,
                              void* d_out, int out_size)
{
    const float* fr    = (const float*)d_in[0];
    const float* ffull = (const float*)d_in[1];
    const float* odor  = (const float*)d_in[2];
    const float* eps   = (const float*)d_in[3];
    const float* Wenc  = (const float*)d_in[4];
    const float* benc  = (const float*)d_in[5];
    const float* mask  = (const float*)d_in[6];
    const float* Wmf   = (const float*)d_in[7];
    const float* Wms   = (const float*)d_in[8];
    const float* bmu   = (const float*)d_in[9];
    const float* Wlf   = (const float*)d_in[10];
    const float* Wls   = (const float*)d_in[11];
    const float* blv   = (const float*)d_in[12];
    const float* Wc    = (const float*)d_in[13];
    const float* We    = (const float*)d_in[14];
    const float* bias  = (const float*)d_in[15];
    const float* tau   = (const float*)d_in[16];
    const float* waff  = (const float*)d_in[17];
    const float* baff  = (const float*)d_in[18];
    const float* scale = (const float*)d_in[19];
    const float* shift = (const float*)d_in[20];
    const float* ctau  = (const float*)d_in[21];
    float* out = (float*)d_out;

    k_main<<<CONV_BLOCKS + SPAR_BLOCKS, 256>>>(fr, odor, Wenc, benc, mask, eps,
                                               Wmf, Wms, bmu, Wlf, Wls, blv,
                                               waff, baff, Wc, We, out);
    k_scan<<<(NN + SCW - 1) / SCW, 32 * SCW>>>(ffull, ctau, scale, shift, out);
    k_rec<<<NN, 256>>>(bias, tau, out);
}

// round 6
// speedup vs baseline: 3.0548x; 1.2807x over previous
#include <cuda_runtime.h>
#include <math.h>

#define NN   302
#define TT   2048
#define TT4  512           // TT / 4
#define KK   33
#define TEX  2080          // TT + KK - 1
#define NOD  16
#define DTs  0.2f
#define CROP 16            // (TEX - TT)/2
#define NTs  ((size_t)NN * TT)
#define NNP  312           // padded row capacity (mult of 8)

#define CONV_BLOCKS  (NN * 8)          // 2416: 8 chunks of 256 t per neuron
#define SPAR_BLOCKS  38                // 8 warps/block, warp-per-row

// ---------------- scratch (static device globals; no allocs) ----------------
__device__ int   g_cnt[2 * NN];        // padded counts (multiple of 4)
__device__ int   g_col[2][NN][NNP];
__device__ float g_valw[2][NN][NNP];

// ============================================================================
// K1: fused sensory-encode + depthwise convs + VAE sample + softplus
//     PLUS sparsification of W_chem/W_elec (extra blocks)
// writes out sections 2,3,4,5,8
// ============================================================================
__global__ void __launch_bounds__(256)
k_main(const float* __restrict__ fr,    // (N, TE)
       const float* __restrict__ odor,  // (16, TE)
       const float* __restrict__ Wenc,  // (N, 16)
       const float* __restrict__ benc,
       const float* __restrict__ mask,
       const float* __restrict__ eps,   // (N, T)
       const float* __restrict__ Wmf, const float* __restrict__ Wms,
       const float* __restrict__ bmu,
       const float* __restrict__ Wlf, const float* __restrict__ Wls,
       const float* __restrict__ blv,
       const float* __restrict__ waff, const float* __restrict__ baff,
       const float* __restrict__ Wc, const float* __restrict__ We,
       float* __restrict__ out)
{
    const int tx = threadIdx.x;

    if (blockIdx.x >= CONV_BLOCKS) {
        // ---------------- sparsify branch: warp per matrix row ----------------
        const int sb   = blockIdx.x - CONV_BLOCKS;
        const int lane = tx & 31;
        const int m    = sb * 8 + (tx >> 5);
        if (m >= NN) return;
        int c0 = 0, c1 = 0;
        for (int jb = 0; jb < NN; jb += 32) {
            const int j = jb + lane;
            float v = (j < NN) ? Wc[m * NN + j] : 0.0f;
            unsigned mk = __ballot_sync(0xffffffffu, v != 0.0f);
            if (v != 0.0f) {
                int p = c0 + __popc(mk & ((1u << lane) - 1u));
                g_col[0][m][p] = j; g_valw[0][m][p] = v;
            }
            c0 += __popc(mk);
            float w = (j < NN) ? We[m * NN + j] : 0.0f;
            mk = __ballot_sync(0xffffffffu, w != 0.0f);
            if (w != 0.0f) {
                int p = c1 + __popc(mk & ((1u << lane) - 1u));
                g_col[1][m][p] = j; g_valw[1][m][p] = w;
            }
            c1 += __popc(mk);
        }
        int c0p = (c0 + 3) & ~3;
        int c1p = (c1 + 3) & ~3;
        if (lane < c0p - c0) { g_col[0][m][c0 + lane] = 0; g_valw[0][m][c0 + lane] = 0.f; }
        if (lane < c1p - c1) { g_col[1][m][c1 + lane] = 0; g_valw[1][m][c1 + lane] = 0.f; }
        if (lane == 0) { g_cnt[m] = c0p; g_cnt[NN + m] = c1p; }
        return;
    }

    // ---------------- conv/sample branch ----------------
    __shared__ float2 s_d[288];            // (fr, sensory_extend)
    __shared__ float4 s_w4[KK];            // (Wmf, Wms, Wlf, Wls) per tap
    const int n  = blockIdx.x >> 3;
    const int t0 = (blockIdx.x & 7) * 256;

    const float msk = mask[n];
    const float be  = benc[n];
    for (int i = tx; i < 288; i += 256) {
        float frv = fr[n * TEX + t0 + i];
        float acc = 0.0f;
#pragma unroll
        for (int o = 0; o < NOD; ++o)
            acc = fmaf(__ldg(&Wenc[n * NOD + o]), odor[o * TEX + t0 + i], acc);
        s_d[i] = make_float2(frv, msk * (acc + be));
    }
    if (tx < KK)
        s_w4[tx] = make_float4(Wmf[n * KK + tx], Wms[n * KK + tx],
                               Wlf[n * KK + tx], Wls[n * KK + tx]);
    __syncthreads();

    const int t = t0 + tx;
    float a = 0.f, b = 0.f, c = 0.f, d = 0.f;
#pragma unroll 11
    for (int k = 0; k < KK; ++k) {
        float2 x = s_d[tx + k];
        float4 w = s_w4[k];
        a = fmaf(x.x, w.x, a);
        b = fmaf(x.y, w.y, b);
        c = fmaf(x.x, w.z, c);
        d = fmaf(x.y, w.w, d);
    }
    float mu = a + b + bmu[n];
    float lv = c + d + blv[n];
    float sv = fmaf(expf(0.5f * lv), eps[n * TT + t], mu);
    float z  = fmaf(waff[n], sv, baff[n]);
    float ca = fmaxf(z, 0.0f) + log1pf(expf(-fabsf(z)));   // stable softplus

    const size_t idx = (size_t)n * TT + t;
    out[2 * NTs + idx] = mu;
    out[3 * NTs + idx] = lv;
    out[4 * NTs + idx] = sv;
    out[5 * NTs + idx] = ca;
    out[8 * NTs + idx] = s_d[tx + CROP].y;
}

// ============================================================================
// K2 (fused): blocks [0, NN)  -> sparse recurrent + voltage update
//             blocks [NN,2NN) -> exponential IIR scan (block per neuron)
// ============================================================================
__global__ void __launch_bounds__(256)
k_epi(const float* __restrict__ bias,
      const float* __restrict__ tau,
      const float* __restrict__ ffull,
      const float* __restrict__ ctau,
      const float* __restrict__ scale,
      const float* __restrict__ shift,
      float* __restrict__ out)
{
    const int tx = threadIdx.x;

    if (blockIdx.x >= NN) {
        // ---------------- scan branch: one block per neuron ----------------
        __shared__ float sbuf[TT + TT / 8];      // P(i) = i + (i>>3), stride-9
        __shared__ float sF[8], sE[8];
        const int n    = blockIdx.x - NN;
        const int w    = tx >> 5;
        const int lane = tx & 31;

        const float* ca = out + 5 * NTs + (size_t)n * TT;
        for (int i = tx; i < TT; i += 256)
            sbuf[i + (i >> 3)] = ca[i];
        __syncthreads();

        const float r = expf(-DTs / ctau[n]);
        float f = r;                      // r^8
        f *= f; f *= f; f *= f;

        // thread-local segment of 8: e = sum_j x[j] * r^(7-j)
        const int base = tx * 9;
        float e = 0.f;
#pragma unroll
        for (int j = 0; j < 8; ++j)
            e = fmaf(r, e, sbuf[base + j]);

        // warp-inclusive scan of affine maps (F, E)
        float F = f, E = e;
#pragma unroll
        for (int dd = 1; dd < 32; dd <<= 1) {
            float Fp = __shfl_up_sync(0xffffffffu, F, dd);
            float Ep = __shfl_up_sync(0xffffffffu, E, dd);
            if (lane >= dd) { E = fmaf(F, Ep, E); F = F * Fp; }
        }
        if (lane == 31) { sF[w] = F; sE[w] = E; }
        __syncthreads();

        // cross-warp prefix map (aggregates of warps 0..w-1), ascending compose
        float Fp = 1.f, Ep = 0.f;
        for (int q = 0; q < w; ++q) {
            Ep = fmaf(sF[q], Ep, sE[q]);
            Fp = Fp * sF[q];
        }

        const float init = (ffull[(size_t)n * TT] - shift[n]) / scale[n];
        const float x0   = init / r;              // m[-1] seed: m[0] = init + ca[0]
        const float pv   = fmaf(Fp, x0, Ep);      // value entering this warp

        // exclusive-within-warp map applied to pv
        float Fe = __shfl_up_sync(0xffffffffu, F, 1);
        float Ee = __shfl_up_sync(0xffffffffu, E, 1);
        float carry = (lane == 0) ? pv : fmaf(Fe, pv, Ee);

        float cacc = carry;
#pragma unroll
        for (int j = 0; j < 8; ++j) {
            cacc = fmaf(r, cacc, sbuf[base + j]);
            sbuf[base + j] = cacc;
        }
        __syncthreads();

        const float sc = scale[n], sh = shift[n];
        float* o6 = out + 6 * NTs + (size_t)n * TT;
        float* o1 = out + 1 * NTs + (size_t)n * TT;
        for (int i = tx; i < TT; i += 256) {
            float m = sbuf[i + (i >> 3)];
            o6[i] = m;
            o1[i] = fmaf(sc, m, sh);
        }
        return;
    }

    // ---------------- recurrent branch: one block per neuron, 8 t/thread ----
    __shared__ int   sc_col[NNP], se_col[NNP];
    __shared__ float sc_val[NNP], se_val[NNP];
    __shared__ int   s_cnt[2];
    const int n = blockIdx.x;
    if (tx < 2) s_cnt[tx] = g_cnt[tx * NN + n];
    __syncthreads();
    const int nc = s_cnt[0], ne = s_cnt[1];
    for (int i = tx; i < nc; i += 256) { sc_col[i] = g_col[0][n][i]; sc_val[i] = g_valw[0][n][i]; }
    for (int i = tx; i < ne; i += 256) { se_col[i] = g_col[1][n][i]; se_val[i] = g_valw[1][n][i]; }
    __syncthreads();

    const float4* sv4 = (const float4*)(out + 4 * NTs);
    const int ta = tx;           // float4 index 0..255
    const int tb = tx + 256;     // float4 index 256..511

    float4 A = make_float4(0.f, 0.f, 0.f, 0.f);
    float4 B = make_float4(0.f, 0.f, 0.f, 0.f);
    for (int i = 0; i < nc; i += 4) {
#pragma unroll
        for (int u = 0; u < 4; ++u) {
            const size_t row = (size_t)sc_col[i + u] * TT4;
            float4 xa = sv4[row + ta];
            float4 xb = sv4[row + tb];
            const float v = sc_val[i + u];
            A.x = fmaf(v, fmaxf(xa.x, 0.f), A.x);
            A.y = fmaf(v, fmaxf(xa.y, 0.f), A.y);
            A.z = fmaf(v, fmaxf(xa.z, 0.f), A.z);
            A.w = fmaf(v, fmaxf(xa.w, 0.f), A.w);
            B.x = fmaf(v, fmaxf(xb.x, 0.f), B.x);
            B.y = fmaf(v, fmaxf(xb.y, 0.f), B.y);
            B.z = fmaf(v, fmaxf(xb.z, 0.f), B.z);
            B.w = fmaf(v, fmaxf(xb.w, 0.f), B.w);
        }
    }
    for (int i = 0; i < ne; i += 4) {
#pragma unroll
        for (int u = 0; u < 4; ++u) {
            const size_t row = (size_t)se_col[i + u] * TT4;
            float4 xa = sv4[row + ta];
            float4 xb = sv4[row + tb];
            const float v = se_val[i + u];
            A.x = fmaf(v, xa.x, A.x);  A.y = fmaf(v, xa.y, A.y);
            A.z = fmaf(v, xa.z, A.z);  A.w = fmaf(v, xa.w, A.w);
            B.x = fmaf(v, xb.x, B.x);  B.y = fmaf(v, xb.y, B.y);
            B.z = fmaf(v, xb.z, B.z);  B.w = fmaf(v, xb.w, B.w);
        }
    }

    const float g  = DTs / tau[n];
    const float bi = bias[n];
    const float4* sen4 = (const float4*)(out + 8 * NTs);
    float4* rec4 = (float4*)(out + 7 * NTs);
    float4* mun4 = (float4*)(out + 0 * NTs);

#pragma unroll
    for (int h = 0; h < 2; ++h) {
        const size_t ridx = (size_t)n * TT4 + (h ? tb : ta);
        float4 acc = h ? B : A;
        float4 sen = sen4[ridx];
        float4 sv  = sv4[ridx];
        float4 rec, mun;
        rec.x = acc.x + sen.x;  rec.y = acc.y + sen.y;
        rec.z = acc.z + sen.z;  rec.w = acc.w + sen.w;
        mun.x = sv.x + g * (-sv.x + rec.x + bi);
        mun.y = sv.y + g * (-sv.y + rec.y + bi);
        mun.z = sv.z + g * (-sv.z + rec.z + bi);
        mun.w = sv.w + g * (-sv.w + rec.w + bi);
        rec4[ridx] = rec;
        mun4[ridx] = mun;
    }
}

// ---------------- launch ----------------------------------------------------
extern "C" void kernel_launch(void* const* d_in, const int* in_sizes, int n_in,
                              void* d_out, int out_size)
{
    const float* fr    = (const float*)d_in[0];
    const float* ffull = (const float*)d_in[1];
    const float* odor  = (const float*)d_in[2];
    const float* eps   = (const float*)d_in[3];
    const float* Wenc  = (const float*)d_in[4];
    const float* benc  = (const float*)d_in[5];
    const float* mask  = (const float*)d_in[6];
    const float* Wmf   = (const float*)d_in[7];
    const float* Wms   = (const float*)d_in[8];
    const float* bmu   = (const float*)d_in[9];
    const float* Wlf   = (const float*)d_in[10];
    const float* Wls   = (const float*)d_in[11];
    const float* blv   = (const float*)d_in[12];
    const float* Wc    = (const float*)d_in[13];
    const float* We    = (const float*)d_in[14];
    const float* bias  = (const float*)d_in[15];
    const float* tau   = (const float*)d_in[16];
    const float* waff  = (const float*)d_in[17];
    const float* baff  = (const float*)d_in[18];
    const float* scale = (const float*)d_in[19];
    const float* shift = (const float*)d_in[20];
    const float* ctau  = (const float*)d_in[21];
    float* out = (float*)d_out;

    k_main<<<CONV_BLOCKS + SPAR_BLOCKS, 256>>>(fr, odor, Wenc, benc, mask, eps,
                                               Wmf, Wms, bmu, Wlf, Wls, blv,
                                               waff, baff, Wc, We, out);
    k_epi<<<2 * NN, 256>>>(bias, tau, ffull, ctau, scale, shift, out);
}